// round 1
// baseline (speedup 1.0000x reference)
#include <cuda_runtime.h>

// Problem constants (from reference): B=2048, Q=128, S=128, H=32, C=Q*S
#define NB 2048
#define NQ 128
#define NS 128
#define NH 32
#define NC (NQ * NS)

#define TPB 256  // threads per block = batches per block

// out[b,q] = W2[q] . elu( x[b, q*S : (q+1)*S] @ W1[q] + b1[q] ) + b2[q]
//
// Block: fixed q = blockIdx.x, batches [blockIdx.y*TPB, +TPB). One thread per batch.
// W1[q] (128x32 fp32 = 16KB) staged in shared memory; inner loop reads it with
// uniform (broadcast) 128-bit LDS and accumulates with packed fma.rn.f32x2
// (2 FMA/lane/instr -> 2x the scalar FFMA throughput on Blackwell).

__global__ __launch_bounds__(TPB, 2) void divenc_kernel(
    const float* __restrict__ x,
    const float* __restrict__ W1,
    const float* __restrict__ b1,
    const float* __restrict__ W2,
    const float* __restrict__ b2,
    float* __restrict__ out)
{
    __shared__ __align__(16) float sW1[NS * NH];  // 16 KB, layout [s][h]
    __shared__ float sB1[NH];
    __shared__ float sW2[NH];
    __shared__ float sB2;

    const int q = blockIdx.x;
    const int b = blockIdx.y * TPB + threadIdx.x;

    // ---- stage W1[q], b1[q], W2[q], b2[q] into smem (coalesced float4) ----
    {
        const float4* gW1 = (const float4*)(W1 + (size_t)q * NS * NH);
        float4* s4 = (float4*)sW1;
        #pragma unroll
        for (int i = 0; i < (NS * NH / 4) / TPB; i++)  // 4096/4/256 = 4 iters
            s4[threadIdx.x + i * TPB] = gW1[threadIdx.x + i * TPB];
        if (threadIdx.x < NH) {
            sB1[threadIdx.x] = b1[q * NH + threadIdx.x];
            sW2[threadIdx.x] = W2[q * NH + threadIdx.x];
        }
        if (threadIdx.x == 0) sB2 = b2[q];
    }
    __syncthreads();

    // ---- packed accumulators: 16 x f32x2 covering h = 0..31 ----
    unsigned long long acc[NH / 2];
    #pragma unroll
    for (int p = 0; p < NH / 2; p++) {
        float lo = sB1[2 * p], hi = sB1[2 * p + 1];
        asm("mov.b64 %0, {%1, %2};" : "=l"(acc[p]) : "f"(lo), "f"(hi));
    }

    const float4* xp = (const float4*)(x + (size_t)b * NC + (size_t)q * NS);

    // ---- mainloop over S in chunks of 4 ----
    #pragma unroll 2
    for (int s4i = 0; s4i < NS / 4; s4i++) {
        float4 xv = xp[s4i];
        #pragma unroll
        for (int j = 0; j < 4; j++) {
            float xs = (j == 0) ? xv.x : (j == 1) ? xv.y : (j == 2) ? xv.z : xv.w;
            unsigned long long xx;
            asm("mov.b64 %0, {%1, %1};" : "=l"(xx) : "f"(xs));
            const ulonglong2* w = (const ulonglong2*)&sW1[(s4i * 4 + j) * NH];
            #pragma unroll
            for (int p = 0; p < 8; p++) {
                ulonglong2 wv = w[p];  // uniform address -> smem broadcast
                asm("fma.rn.f32x2 %0, %1, %2, %0;" : "+l"(acc[2 * p])     : "l"(xx), "l"(wv.x));
                asm("fma.rn.f32x2 %0, %1, %2, %0;" : "+l"(acc[2 * p + 1]) : "l"(xx), "l"(wv.y));
            }
        }
    }

    // ---- epilogue: ELU + dot with W2 + b2 ----
    float r = sB2;
    #pragma unroll
    for (int p = 0; p < NH / 2; p++) {
        float v0, v1;
        asm("mov.b64 {%0, %1}, %2;" : "=f"(v0), "=f"(v1) : "l"(acc[p]));
        float h0 = (v0 > 0.0f) ? v0 : (__expf(v0) - 1.0f);
        float h1 = (v1 > 0.0f) ? v1 : (__expf(v1) - 1.0f);
        r += h0 * sW2[2 * p] + h1 * sW2[2 * p + 1];
    }
    out[(size_t)b * NQ + q] = r;
}

extern "C" void kernel_launch(void* const* d_in, const int* in_sizes, int n_in,
                              void* d_out, int out_size) {
    // metadata order == setup_inputs dict order: x, W1, b1, W2, b2 (all float32)
    const float* x  = (const float*)d_in[0];
    const float* W1 = (const float*)d_in[1];
    const float* b1 = (const float*)d_in[2];
    const float* W2 = (const float*)d_in[3];
    const float* b2 = (const float*)d_in[4];
    float* out = (float*)d_out;

    dim3 grid(NQ, NB / TPB);  // 128 x 8 = 1024 blocks
    divenc_kernel<<<grid, TPB>>>(x, W1, b1, W2, b2, out);
}

// round 2
// speedup vs baseline: 1.3702x; 1.3702x over previous
#include <cuda_runtime.h>

// B=2048, Q=128, S=128, H=32
#define NB 2048
#define NQ 128
#define NS 128
#define NH 32
#define NC (NQ * NS)

#define TPB 128   // threads per block
#define BPB 256   // batches per block (2 per thread)
#define SCH 16    // s-tile size
#define NTILE (NS / SCH)
#define XSTR 5    // float4 stride per staged x row (4 data + 1 pad)

typedef unsigned long long ull;

// out[b,q] = W2[q] . elu( x[b, q*S:(q+1)*S] @ W1[q] + b1[q] ) + b2[q]
//
// Block: fixed q, 256 batches, 2 batches per thread (each broadcast W-load
// feeds 4 packed FMAs). x is staged through smem in 16-wide s-tiles with
// 64B-coalesced global loads (8 wavefronts/LDG.128 instead of 32).

__global__ __launch_bounds__(TPB) void divenc_kernel(
    const float* __restrict__ x,
    const float* __restrict__ W1,
    const float* __restrict__ b1,
    const float* __restrict__ W2,
    const float* __restrict__ b2,
    float* __restrict__ out)
{
    __shared__ __align__(16) float sW1[NS * NH];     // 16 KB, [s][h]
    __shared__ __align__(16) float4 sX[BPB * XSTR];  // 20 KB, padded rows
    __shared__ float sB1[NH];
    __shared__ float sW2[NH];
    __shared__ float sB2;

    const int q = blockIdx.x;
    const int t = threadIdx.x;
    const int bbase = blockIdx.y * BPB;

    // ---- stage W1[q] + biases (coalesced float4) ----
    {
        const float4* gW1 = (const float4*)(W1 + (size_t)q * NS * NH);
        float4* s4w = (float4*)sW1;
        #pragma unroll
        for (int i = 0; i < (NS * NH / 4) / TPB; i++)  // 8 iters
            s4w[t + i * TPB] = gW1[t + i * TPB];
        if (t < NH) {
            sB1[t] = b1[q * NH + t];
            sW2[t] = W2[q * NH + t];
        }
        if (t == 0) sB2 = b2[q];
    }
    __syncthreads();

    // ---- packed accumulators: 2 batches x 16 f32x2 (h=0..31) ----
    ull acc0[16], acc1[16];
    #pragma unroll
    for (int p = 0; p < 16; p++) {
        float lo = sB1[2 * p], hi = sB1[2 * p + 1];
        ull a;
        asm("mov.b64 %0, {%1, %2};" : "=l"(a) : "f"(lo), "f"(hi));
        acc0[p] = a;
        acc1[p] = a;
    }

    const float* xg0 = x + (size_t)bbase * NC + (size_t)q * NS;

    for (int tile = 0; tile < NTILE; tile++) {
        const int s0 = tile * SCH;

        // ---- stage x tile: 256 rows x 16 floats, 64B coalesced per row ----
        #pragma unroll
        for (int i = 0; i < (BPB * 4) / TPB; i++) {  // 8 iters
            int idx = i * TPB + t;
            int row = idx >> 2, col = idx & 3;
            sX[row * XSTR + col] =
                *(const float4*)(xg0 + (size_t)row * NC + s0 + col * 4);
        }
        __syncthreads();

        const float4* xr0 = &sX[t * XSTR];
        const float4* xr1 = &sX[(t + TPB) * XSTR];

        #pragma unroll
        for (int s4 = 0; s4 < SCH / 4; s4++) {
            float4 xv0 = xr0[s4];
            float4 xv1 = xr1[s4];
            #pragma unroll
            for (int j = 0; j < 4; j++) {
                float a0 = (j == 0) ? xv0.x : (j == 1) ? xv0.y : (j == 2) ? xv0.z : xv0.w;
                float a1 = (j == 0) ? xv1.x : (j == 1) ? xv1.y : (j == 2) ? xv1.z : xv1.w;
                ull xx0, xx1;
                asm("mov.b64 %0, {%1, %1};" : "=l"(xx0) : "f"(a0));
                asm("mov.b64 %0, {%1, %1};" : "=l"(xx1) : "f"(a1));
                const ulonglong2* w = (const ulonglong2*)&sW1[(s0 + s4 * 4 + j) * NH];
                #pragma unroll
                for (int p = 0; p < 8; p++) {
                    ulonglong2 wv = w[p];  // uniform address -> broadcast, 1 phase
                    asm("fma.rn.f32x2 %0, %1, %2, %0;" : "+l"(acc0[2 * p])     : "l"(xx0), "l"(wv.x));
                    asm("fma.rn.f32x2 %0, %1, %2, %0;" : "+l"(acc0[2 * p + 1]) : "l"(xx0), "l"(wv.y));
                    asm("fma.rn.f32x2 %0, %1, %2, %0;" : "+l"(acc1[2 * p])     : "l"(xx1), "l"(wv.x));
                    asm("fma.rn.f32x2 %0, %1, %2, %0;" : "+l"(acc1[2 * p + 1]) : "l"(xx1), "l"(wv.y));
                }
            }
        }
        __syncthreads();
    }

    // ---- epilogue: ELU + dot with W2 + b2 for both batches ----
    float r0 = sB2, r1 = sB2;
    #pragma unroll
    for (int p = 0; p < 16; p++) {
        float v0, v1, u0, u1;
        asm("mov.b64 {%0, %1}, %2;" : "=f"(v0), "=f"(v1) : "l"(acc0[p]));
        asm("mov.b64 {%0, %1}, %2;" : "=f"(u0), "=f"(u1) : "l"(acc1[p]));
        float w0 = sW2[2 * p], w1 = sW2[2 * p + 1];
        float h00 = (v0 > 0.0f) ? v0 : (__expf(v0) - 1.0f);
        float h01 = (v1 > 0.0f) ? v1 : (__expf(v1) - 1.0f);
        float h10 = (u0 > 0.0f) ? u0 : (__expf(u0) - 1.0f);
        float h11 = (u1 > 0.0f) ? u1 : (__expf(u1) - 1.0f);
        r0 += h00 * w0 + h01 * w1;
        r1 += h10 * w0 + h11 * w1;
    }
    out[(size_t)(bbase + t) * NQ + q] = r0;
    out[(size_t)(bbase + TPB + t) * NQ + q] = r1;
}

extern "C" void kernel_launch(void* const* d_in, const int* in_sizes, int n_in,
                              void* d_out, int out_size) {
    const float* x  = (const float*)d_in[0];
    const float* W1 = (const float*)d_in[1];
    const float* b1 = (const float*)d_in[2];
    const float* W2 = (const float*)d_in[3];
    const float* b2 = (const float*)d_in[4];
    float* out = (float*)d_out;

    dim3 grid(NQ, NB / BPB);  // 128 x 8 = 1024 blocks
    divenc_kernel<<<grid, TPB>>>(x, W1, b1, W2, b2, out);
}

// round 5
// speedup vs baseline: 1.8270x; 1.3333x over previous
#include <cuda_runtime.h>
#include <cuda_bf16.h>
#include <cstdint>

// B=2048, Q=128, S=128(K), H=32(N)
#define NB 2048
#define NQ 128
#define NS 128
#define NH 32
#define NC (NQ * NS)
#define TPB 128
#define KH 64          // K columns per phase (2 phases)
#define PA 72          // bf16 pitch of A rows (144B: conflict-free for LDSM)
#define PB 72          // bf16 pitch of B rows

__device__ __forceinline__ uint32_t smem_u32(const void* p) {
    uint32_t a;
    asm("{ .reg .u64 t; cvta.to.shared.u64 t, %1; cvt.u32.u64 %0, t; }" : "=r"(a) : "l"(p));
    return a;
}

__device__ __forceinline__ void ldsm4(uint32_t* r, uint32_t addr) {
    asm volatile("ldmatrix.sync.aligned.m8n8.x4.shared.b16 {%0,%1,%2,%3}, [%4];"
                 : "=r"(r[0]), "=r"(r[1]), "=r"(r[2]), "=r"(r[3]) : "r"(addr));
}
__device__ __forceinline__ void mma_bf16(float* d, const uint32_t* a, uint32_t b0, uint32_t b1) {
    asm volatile(
        "mma.sync.aligned.m16n8k16.row.col.f32.bf16.bf16.f32 "
        "{%0,%1,%2,%3}, {%4,%5,%6,%7}, {%8,%9}, {%0,%1,%2,%3};"
        : "+f"(d[0]), "+f"(d[1]), "+f"(d[2]), "+f"(d[3])
        : "r"(a[0]), "r"(a[1]), "r"(a[2]), "r"(a[3]), "r"(b0), "r"(b1));
}
// pack {hi half = y, lo half = x} as bf16x2
__device__ __forceinline__ uint32_t bf2pack(float x, float y) {
    uint32_t r;
    asm("cvt.rn.bf16x2.f32 %0, %1, %2;" : "=r"(r) : "f"(y), "f"(x));
    return r;
}

// out[b,q] = W2[q] . elu( x[b, q*S:(q+1)*S] @ W1[q] + b1[q] ) + b2[q]
// Block: one q, 128 batches. M=128 N=32 K=128 GEMM via mma.sync bf16,
// fp32 accuracy with 3-term bf16 split (Ahi*Bhi + Ahi*Blo + Alo*Bhi).
__global__ __launch_bounds__(TPB) void divenc_mma(
    const float* __restrict__ x, const float* __restrict__ W1,
    const float* __restrict__ b1, const float* __restrict__ W2,
    const float* __restrict__ b2, float* __restrict__ out)
{
    __shared__ __align__(16) __nv_bfloat16 sAhi[128 * PA];  // 18KB
    __shared__ __align__(16) __nv_bfloat16 sAlo[128 * PA];  // 18KB
    __shared__ __align__(16) __nv_bfloat16 sBhi[NH * PB];   // 4.5KB
    __shared__ __align__(16) __nv_bfloat16 sBlo[NH * PB];   // 4.5KB
    __shared__ float sB1[NH], sW2[NH];
    __shared__ float sB2v;

    const int q = blockIdx.x;
    const int bt = blockIdx.y;
    const int t = threadIdx.x;
    const int w = t >> 5;
    const int l = t & 31;

    if (t < NH) { sB1[t] = b1[q * NH + t]; sW2[t] = W2[q * NH + t]; }
    if (t == 0) sB2v = b2[q];

    float acc[2][4][4];
    #pragma unroll
    for (int mi = 0; mi < 2; mi++)
        #pragma unroll
        for (int nj = 0; nj < 4; nj++)
            #pragma unroll
            for (int c = 0; c < 4; c++) acc[mi][nj][c] = 0.0f;

    // ldmatrix lane addressing (both A and B non-trans):
    // lanes 0-15 -> rows 0-15 at k-offset 0; lanes 16-31 -> rows 0-15 at k-offset 8.
    // A: matrices {m0,m1,m2,m3} = {r0-7 k0-7, r8-15 k0-7, r0-7 k8-15, r8-15 k8-15}
    //    == mma A frag order directly.
    // B (smem [n][k]): m0=(n0-7,k0-7) m1=(n8-15,k0-7) m2=(n0-7,k8-15) m3=(n8-15,k8-15);
    //    n-tile j in {0..3}: b0 = reg j of (load0|load1), b1 = matching k8-15 reg.
    const int lr = l & 15;
    const int lk = (l >> 4) * 8;
    const uint32_t aHiB = smem_u32(sAhi), aLoB = smem_u32(sAlo);
    const uint32_t bHiB = smem_u32(sBhi), bLoB = smem_u32(sBlo);
    const uint32_t aOff0 = (uint32_t)((w * 32 + lr) * PA + lk) * 2;
    const uint32_t aOff1 = (uint32_t)((w * 32 + 16 + lr) * PA + lk) * 2;
    const uint32_t bOff0 = (uint32_t)((lr) * PB + lk) * 2;        // n 0-15
    const uint32_t bOff1 = (uint32_t)((16 + lr) * PB + lk) * 2;   // n 16-31

    const float* xg = x + (size_t)bt * 128 * NC + (size_t)q * NS;
    const float* gW = W1 + (size_t)q * NS * NH;

    for (int p = 0; p < 2; p++) {
        // ---- stage A: 128 rows x 64 k, hi/lo bf16, coalesced 256B row segments ----
        #pragma unroll
        for (int i = 0; i < 16; i++) {
            int idx = i * TPB + t;
            int row = idx >> 4, c4 = idx & 15;
            float4 v = *(const float4*)(xg + (size_t)row * NC + p * KH + c4 * 4);
            uint32_t h01 = bf2pack(v.x, v.y);
            uint32_t h23 = bf2pack(v.z, v.w);
            float e0 = v.x - __uint_as_float(h01 << 16);
            float e1 = v.y - __uint_as_float(h01 & 0xFFFF0000u);
            float e2 = v.z - __uint_as_float(h23 << 16);
            float e3 = v.w - __uint_as_float(h23 & 0xFFFF0000u);
            uint32_t l01 = bf2pack(e0, e1);
            uint32_t l23 = bf2pack(e2, e3);
            *(uint2*)(sAhi + row * PA + c4 * 4) = make_uint2(h01, h23);
            *(uint2*)(sAlo + row * PA + c4 * 4) = make_uint2(l01, l23);
        }
        // ---- stage B = W1^T slice: [h][k], hi/lo bf16 ----
        #pragma unroll
        for (int i = 0; i < 16; i++) {
            int idx = i * TPB + t;
            int k = idx >> 5, h = idx & 31;
            float wv = gW[(p * KH + k) * NH + h];  // == gW[p*KH*NH + idx], coalesced
            __nv_bfloat16 whi = __float2bfloat16_rn(wv);
            __nv_bfloat16 wlo = __float2bfloat16_rn(wv - __bfloat162float(whi));
            sBhi[h * PB + k] = whi;
            sBlo[h * PB + k] = wlo;
        }
        __syncthreads();

        // ---- mma mainloop: 4 k16 steps ----
        #pragma unroll
        for (int ks = 0; ks < 4; ks++) {
            const uint32_t ko = ks * 32;  // 16 bf16 = 32 bytes
            uint32_t ah0[4], ah1[4], al0[4], al1[4];
            uint32_t bh0[4], bh1[4], bl0[4], bl1[4];
            ldsm4(ah0, aHiB + aOff0 + ko);
            ldsm4(ah1, aHiB + aOff1 + ko);
            ldsm4(al0, aLoB + aOff0 + ko);
            ldsm4(al1, aLoB + aOff1 + ko);
            ldsm4(bh0, bHiB + bOff0 + ko);   // non-trans: smem already [n][k]
            ldsm4(bh1, bHiB + bOff1 + ko);
            ldsm4(bl0, bLoB + bOff0 + ko);
            ldsm4(bl1, bLoB + bOff1 + ko);
            // n-tile j: b0 (k0-7) and b1 (k8-15)
            uint32_t bh_0[4] = {bh0[0], bh0[1], bh1[0], bh1[1]};
            uint32_t bh_1[4] = {bh0[2], bh0[3], bh1[2], bh1[3]};
            uint32_t bl_0[4] = {bl0[0], bl0[1], bl1[0], bl1[1]};
            uint32_t bl_1[4] = {bl0[2], bl0[3], bl1[2], bl1[3]};
            #pragma unroll
            for (int nj = 0; nj < 4; nj++) {
                mma_bf16(acc[0][nj], ah0, bh_0[nj], bh_1[nj]);
                mma_bf16(acc[1][nj], ah1, bh_0[nj], bh_1[nj]);
                mma_bf16(acc[0][nj], ah0, bl_0[nj], bl_1[nj]);
                mma_bf16(acc[1][nj], ah1, bl_0[nj], bl_1[nj]);
                mma_bf16(acc[0][nj], al0, bh_0[nj], bh_1[nj]);
                mma_bf16(acc[1][nj], al1, bh_0[nj], bh_1[nj]);
            }
        }
        __syncthreads();
    }

    // ---- epilogue: +b1, ELU, dot W2, quad-reduce, store ----
    const int g = l >> 2;    // row within m16 tile (D frag: row = lane/4)
    const int qd = l & 3;    // quad position -> h column pair
    #pragma unroll
    for (int mi = 0; mi < 2; mi++) {
        float pa = 0.0f, pb = 0.0f;
        #pragma unroll
        for (int nj = 0; nj < 4; nj++) {
            int h0 = nj * 8 + qd * 2, h1 = h0 + 1;
            float b10 = sB1[h0], b11 = sB1[h1];
            float w20 = sW2[h0], w21 = sW2[h1];
            float v0 = acc[mi][nj][0] + b10;
            float v1 = acc[mi][nj][1] + b11;
            float v2 = acc[mi][nj][2] + b10;
            float v3 = acc[mi][nj][3] + b11;
            pa += ((v0 > 0.0f) ? v0 : (__expf(v0) - 1.0f)) * w20;
            pa += ((v1 > 0.0f) ? v1 : (__expf(v1) - 1.0f)) * w21;
            pb += ((v2 > 0.0f) ? v2 : (__expf(v2) - 1.0f)) * w20;
            pb += ((v3 > 0.0f) ? v3 : (__expf(v3) - 1.0f)) * w21;
        }
        pa += __shfl_xor_sync(0xFFFFFFFFu, pa, 1);
        pa += __shfl_xor_sync(0xFFFFFFFFu, pa, 2);
        pb += __shfl_xor_sync(0xFFFFFFFFu, pb, 1);
        pb += __shfl_xor_sync(0xFFFFFFFFu, pb, 2);
        if (qd == 0) {
            int r0 = w * 32 + mi * 16 + g;
            out[((size_t)bt * 128 + r0) * NQ + q] = pa + sB2v;
            out[((size_t)bt * 128 + r0 + 8) * NQ + q] = pb + sB2v;
        }
    }
}

extern "C" void kernel_launch(void* const* d_in, const int* in_sizes, int n_in,
                              void* d_out, int out_size) {
    const float* x  = (const float*)d_in[0];
    const float* W1 = (const float*)d_in[1];
    const float* b1 = (const float*)d_in[2];
    const float* W2 = (const float*)d_in[3];
    const float* b2 = (const float*)d_in[4];
    float* out = (float*)d_out;

    dim3 grid(NQ, NB / 128);  // 128 q x 16 batch tiles
    divenc_mma<<<grid, TPB>>>(x, W1, b1, W2, b2, out);
}

// round 6
// speedup vs baseline: 2.3403x; 1.2809x over previous
#include <cuda_runtime.h>
#include <cuda_bf16.h>
#include <cstdint>

// B=2048, Q=128, S=128(K), H=32(N)
#define NB 2048
#define NQ 128
#define NS 128
#define NH 32
#define NC (NQ * NS)
#define TPB 128
#define PAW 40    // A pitch in bf16 (80B rows: LDSM conflict-free)
#define PBK 136   // B pitch in bf16 (272B rows: LDSM conflict-free), full K=128

__device__ __forceinline__ uint32_t smem_u32(const void* p) {
    uint32_t a;
    asm("{ .reg .u64 t; cvta.to.shared.u64 t, %1; cvt.u32.u64 %0, t; }" : "=r"(a) : "l"(p));
    return a;
}
__device__ __forceinline__ void ldsm4(uint32_t* r, uint32_t addr) {
    asm volatile("ldmatrix.sync.aligned.m8n8.x4.shared.b16 {%0,%1,%2,%3}, [%4];"
                 : "=r"(r[0]), "=r"(r[1]), "=r"(r[2]), "=r"(r[3]) : "r"(addr));
}
__device__ __forceinline__ void mma_bf16(float* d, const uint32_t* a, uint32_t b0, uint32_t b1) {
    asm volatile(
        "mma.sync.aligned.m16n8k16.row.col.f32.bf16.bf16.f32 "
        "{%0,%1,%2,%3}, {%4,%5,%6,%7}, {%8,%9}, {%0,%1,%2,%3};"
        : "+f"(d[0]), "+f"(d[1]), "+f"(d[2]), "+f"(d[3])
        : "r"(a[0]), "r"(a[1]), "r"(a[2]), "r"(a[3]), "r"(b0), "r"(b1));
}
// pack {hi half = y, lo half = x} as bf16x2
__device__ __forceinline__ uint32_t bf2pack(float x, float y) {
    uint32_t r;
    asm("cvt.rn.bf16x2.f32 %0, %1, %2;" : "=r"(r) : "f"(y), "f"(x));
    return r;
}

// out[b,q] = W2[q] . elu( x[b, q*S:(q+1)*S] @ W1[q] + b1[q] ) + b2[q]
// Block: one q, 128 batches, 4 warps; warp w owns M-rows [32w, 32w+32).
// Sync-free mainloop: warp-private A staging + register prefetch of the
// next K=32 chunk; B (W1 hi/lo bf16) staged once for the whole K.
__global__ __launch_bounds__(TPB, 4) void divenc_mma(
    const float* __restrict__ x, const float* __restrict__ W1,
    const float* __restrict__ b1, const float* __restrict__ W2,
    const float* __restrict__ b2, float* __restrict__ out)
{
    __shared__ __align__(16) __nv_bfloat16 sAhi[4][32 * PAW];  // 10.2KB
    __shared__ __align__(16) __nv_bfloat16 sAlo[4][32 * PAW];  // 10.2KB
    __shared__ __align__(16) __nv_bfloat16 sBhi[NH * PBK];     // 8.7KB
    __shared__ __align__(16) __nv_bfloat16 sBlo[NH * PBK];     // 8.7KB
    __shared__ float sB1[NH], sW2[NH];
    __shared__ float sB2v;

    const int q = blockIdx.x;
    const int bt = blockIdx.y;
    const int t = threadIdx.x;
    const int w = t >> 5;
    const int l = t & 31;

    // ---- stage B = W1[q]^T full-K (hi/lo bf16), once ----
    const float* gW = W1 + (size_t)q * NS * NH;
    #pragma unroll
    for (int i = 0; i < (NS * NH) / TPB; i++) {  // 32 iters
        int idx = i * TPB + t;
        int k = idx >> 5, h = idx & 31;          // gW layout [k][h], coalesced read
        float wv = gW[idx];
        __nv_bfloat16 whi = __float2bfloat16_rn(wv);
        __nv_bfloat16 wlo = __float2bfloat16_rn(wv - __bfloat162float(whi));
        sBhi[h * PBK + k] = whi;
        sBlo[h * PBK + k] = wlo;
    }
    if (t < NH) { sB1[t] = b1[q * NH + t]; sW2[t] = W2[q * NH + t]; }
    if (t == 0) sB2v = b2[q];
    __syncthreads();   // the ONLY block-wide barrier

    float acc[2][4][4];
    #pragma unroll
    for (int mi = 0; mi < 2; mi++)
        #pragma unroll
        for (int nj = 0; nj < 4; nj++)
            #pragma unroll
            for (int c = 0; c < 4; c++) acc[mi][nj][c] = 0.0f;

    // ldmatrix lane addressing (non-trans, same verified mapping as R5)
    const int lr = l & 15;
    const int lk = (l >> 4) * 8;
    const uint32_t aHi = smem_u32(&sAhi[w][0]);
    const uint32_t aLo = smem_u32(&sAlo[w][0]);
    const uint32_t bHi = smem_u32(sBhi), bLo = smem_u32(sBlo);

    // LDG/STS mapping: instr i covers warp-local rows 4i..4i+3;
    // lane l -> row 4i + (l>>3), cols (l&7)*4 .. +3 (coalesced 128B row-chunks)
    const int rl = l >> 3;
    const int cl = (l & 7) * 4;
    const float* xr = x + (size_t)bt * 128 * NC + (size_t)(32 * w + rl) * NC
                        + (size_t)q * NS + cl;

    float4 g[8];
    #pragma unroll
    for (int i = 0; i < 8; i++)
        g[i] = *(const float4*)(xr + (size_t)(4 * i) * NC);  // chunk 0

    for (int c = 0; c < 4; c++) {
        // ---- convert + STS this chunk into warp-private region ----
        #pragma unroll
        for (int i = 0; i < 8; i++) {
            float4 v = g[i];
            uint32_t h01 = bf2pack(v.x, v.y);
            uint32_t h23 = bf2pack(v.z, v.w);
            float e0 = v.x - __uint_as_float(h01 << 16);
            float e1 = v.y - __uint_as_float(h01 & 0xFFFF0000u);
            float e2 = v.z - __uint_as_float(h23 << 16);
            float e3 = v.w - __uint_as_float(h23 & 0xFFFF0000u);
            uint32_t l01 = bf2pack(e0, e1);
            uint32_t l23 = bf2pack(e2, e3);
            int ro = (4 * i + rl) * PAW + cl;
            *(uint2*)(&sAhi[w][ro]) = make_uint2(h01, h23);
            *(uint2*)(&sAlo[w][ro]) = make_uint2(l01, l23);
        }
        // ---- prefetch next chunk: DRAM latency hides under this chunk's MMAs ----
        if (c < 3) {
            #pragma unroll
            for (int i = 0; i < 8; i++)
                g[i] = *(const float4*)(xr + (size_t)(4 * i) * NC + (c + 1) * 32);
        }
        __syncwarp();

        // ---- 2 k16 steps of MMA ----
        #pragma unroll
        for (int ks = 0; ks < 2; ks++) {
            const uint32_t aoff = (uint32_t)(lr * PAW + ks * 16 + lk) * 2;
            const uint32_t kg = (uint32_t)(c * 32 + ks * 16 + lk);
            const uint32_t boff = (uint32_t)(lr * PBK + kg) * 2;
            uint32_t ah0[4], ah1[4], al0[4], al1[4];
            uint32_t bh0[4], bh1[4], bl0[4], bl1[4];
            ldsm4(ah0, aHi + aoff);
            ldsm4(ah1, aHi + aoff + 16 * PAW * 2);
            ldsm4(al0, aLo + aoff);
            ldsm4(al1, aLo + aoff + 16 * PAW * 2);
            ldsm4(bh0, bHi + boff);
            ldsm4(bh1, bHi + boff + 16 * PBK * 2);
            ldsm4(bl0, bLo + boff);
            ldsm4(bl1, bLo + boff + 16 * PBK * 2);
            uint32_t bh_0[4] = {bh0[0], bh0[1], bh1[0], bh1[1]};
            uint32_t bh_1[4] = {bh0[2], bh0[3], bh1[2], bh1[3]};
            uint32_t bl_0[4] = {bl0[0], bl0[1], bl1[0], bl1[1]};
            uint32_t bl_1[4] = {bl0[2], bl0[3], bl1[2], bl1[3]};
            #pragma unroll
            for (int nj = 0; nj < 4; nj++) {
                mma_bf16(acc[0][nj], ah0, bh_0[nj], bh_1[nj]);
                mma_bf16(acc[1][nj], ah1, bh_0[nj], bh_1[nj]);
                mma_bf16(acc[0][nj], ah0, bl_0[nj], bl_1[nj]);
                mma_bf16(acc[1][nj], ah1, bl_0[nj], bl_1[nj]);
                mma_bf16(acc[0][nj], al0, bh_0[nj], bh_1[nj]);
                mma_bf16(acc[1][nj], al1, bh_0[nj], bh_1[nj]);
            }
        }
        __syncwarp();  // LDSM of chunk c done before STS of chunk c+1
    }

    // ---- epilogue: +b1, ELU, dot W2, quad-reduce, store ----
    const int gg = l >> 2;
    const int qd = l & 3;
    #pragma unroll
    for (int mi = 0; mi < 2; mi++) {
        float pa = 0.0f, pb = 0.0f;
        #pragma unroll
        for (int nj = 0; nj < 4; nj++) {
            int h0 = nj * 8 + qd * 2, h1 = h0 + 1;
            float b10 = sB1[h0], b11 = sB1[h1];
            float w20 = sW2[h0], w21 = sW2[h1];
            float v0 = acc[mi][nj][0] + b10;
            float v1 = acc[mi][nj][1] + b11;
            float v2 = acc[mi][nj][2] + b10;
            float v3 = acc[mi][nj][3] + b11;
            pa += ((v0 > 0.0f) ? v0 : (__expf(v0) - 1.0f)) * w20;
            pa += ((v1 > 0.0f) ? v1 : (__expf(v1) - 1.0f)) * w21;
            pb += ((v2 > 0.0f) ? v2 : (__expf(v2) - 1.0f)) * w20;
            pb += ((v3 > 0.0f) ? v3 : (__expf(v3) - 1.0f)) * w21;
        }
        pa += __shfl_xor_sync(0xFFFFFFFFu, pa, 1);
        pa += __shfl_xor_sync(0xFFFFFFFFu, pa, 2);
        pb += __shfl_xor_sync(0xFFFFFFFFu, pb, 1);
        pb += __shfl_xor_sync(0xFFFFFFFFu, pb, 2);
        if (qd == 0) {
            int r0 = w * 32 + mi * 16 + gg;
            out[((size_t)bt * 128 + r0) * NQ + q] = pa + sB2v;
            out[((size_t)bt * 128 + r0 + 8) * NQ + q] = pb + sB2v;
        }
    }
}

extern "C" void kernel_launch(void* const* d_in, const int* in_sizes, int n_in,
                              void* d_out, int out_size) {
    const float* x  = (const float*)d_in[0];
    const float* W1 = (const float*)d_in[1];
    const float* b1 = (const float*)d_in[2];
    const float* W2 = (const float*)d_in[3];
    const float* b2 = (const float*)d_in[4];
    float* out = (float*)d_out;

    dim3 grid(NQ, NB / 128);  // 128 q x 16 batch tiles
    divenc_mma<<<grid, TPB>>>(x, W1, b1, W2, b2, out);
}

// round 7
// speedup vs baseline: 2.4645x; 1.0531x over previous
#include <cuda_runtime.h>
#include <cuda_bf16.h>
#include <cstdint>

// B=2048, Q=128, S=128(K), H=32(N)
#define NB 2048
#define NQ 128
#define NS 128
#define NH 32
#define NC (NQ * NS)
#define TPB 128

__device__ __forceinline__ uint32_t smem_u32(const void* p) {
    uint32_t a;
    asm("{ .reg .u64 t; cvta.to.shared.u64 t, %1; cvt.u32.u64 %0, t; }" : "=r"(a) : "l"(p));
    return a;
}
__device__ __forceinline__ void ldsm4(uint32_t* r, uint32_t addr) {
    asm volatile("ldmatrix.sync.aligned.m8n8.x4.shared.b16 {%0,%1,%2,%3}, [%4];"
                 : "=r"(r[0]), "=r"(r[1]), "=r"(r[2]), "=r"(r[3]) : "r"(addr));
}
__device__ __forceinline__ void mma_bf16(float* d, const uint32_t* a, uint32_t b0, uint32_t b1) {
    asm volatile(
        "mma.sync.aligned.m16n8k16.row.col.f32.bf16.bf16.f32 "
        "{%0,%1,%2,%3}, {%4,%5,%6,%7}, {%8,%9}, {%0,%1,%2,%3};"
        : "+f"(d[0]), "+f"(d[1]), "+f"(d[2]), "+f"(d[3])
        : "r"(a[0]), "r"(a[1]), "r"(a[2]), "r"(a[3]), "r"(b0), "r"(b1));
}
// pack {hi half = y, lo half = x} as bf16x2
__device__ __forceinline__ uint32_t bf2pack(float x, float y) {
    uint32_t r;
    asm("cvt.rn.bf16x2.f32 %0, %1, %2;" : "=r"(r) : "f"(y), "f"(x));
    return r;
}

// A smem: per-warp 32 rows x 64B (32 k bf16), swizzle granule g^((r>>1)&3).
//   byte(r, kb) = r*64 + (((kb>>4) ^ ((r>>1)&3))<<4) + (kb&15)
//   -> STS.64 conflict-free (phase rows land on disjoint granule halves)
//   -> LDSM conflict-free (8 rows per tile hit 8 distinct banks)
// B smem: 32 rows x 256B (full K=128 bf16), swizzle g^(r&7). Same proofs.

__global__ __launch_bounds__(TPB, 4) void divenc_mma(
    const float* __restrict__ x, const float* __restrict__ W1,
    const float* __restrict__ b1, const float* __restrict__ W2,
    const float* __restrict__ b2, float* __restrict__ out)
{
    __shared__ __align__(16) __nv_bfloat16 sAhi[4][32 * 32];  // 8KB
    __shared__ __align__(16) __nv_bfloat16 sAlo[4][32 * 32];  // 8KB
    __shared__ __align__(16) __nv_bfloat16 sBhi[NH * NS];     // 8KB
    __shared__ __align__(16) __nv_bfloat16 sBlo[NH * NS];     // 8KB
    __shared__ float sB1[NH], sW2[NH];
    __shared__ float sB2v;

    const int q = blockIdx.x;
    const int bt = blockIdx.y;
    const int t = threadIdx.x;
    const int w = t >> 5;
    const int l = t & 31;

    // ---- stage B = W1[q]^T full-K (hi/lo bf16, swizzled), once ----
    const float* gW = W1 + (size_t)q * NS * NH;
    char* bHiC = (char*)sBhi;
    char* bLoC = (char*)sBlo;
    #pragma unroll
    for (int i = 0; i < (NS * NH) / TPB; i++) {  // 32 iters
        int idx = i * TPB + t;
        int k = idx >> 5, h = idx & 31;          // gW layout [k][h], coalesced read
        float wv = gW[idx];
        __nv_bfloat16 whi = __float2bfloat16_rn(wv);
        __nv_bfloat16 wlo = __float2bfloat16_rn(wv - __bfloat162float(whi));
        int kb = 2 * k;
        int sw = h * 256 + ((((kb >> 4) ^ (h & 7)) << 4)) + (kb & 15);
        *(__nv_bfloat16*)(bHiC + sw) = whi;
        *(__nv_bfloat16*)(bLoC + sw) = wlo;
    }
    if (t < NH) { sB1[t] = b1[q * NH + t]; sW2[t] = W2[q * NH + t]; }
    if (t == 0) sB2v = b2[q];
    __syncthreads();   // the ONLY block-wide barrier

    float acc[2][4][4];
    #pragma unroll
    for (int mi = 0; mi < 2; mi++)
        #pragma unroll
        for (int nj = 0; nj < 4; nj++)
            #pragma unroll
            for (int c = 0; c < 4; c++) acc[mi][nj][c] = 0.0f;

    // ldmatrix lane params (non-trans, verified mapping)
    const int lr = l & 15;
    const int lkg = l >> 4;       // k-granule half: 0 -> k0-7, 1 -> k8-15
    const uint32_t vA = (uint32_t)((lr >> 1) & 3);
    const uint32_t vB = (uint32_t)(lr & 7);
    const uint32_t aHi = smem_u32(&sAhi[w][0]) + (uint32_t)lr * 64;
    const uint32_t aLo = smem_u32(&sAlo[w][0]) + (uint32_t)lr * 64;
    const uint32_t bHi = smem_u32(sBhi) + (uint32_t)lr * 256;
    const uint32_t bLo = smem_u32(sBlo) + (uint32_t)lr * 256;

    // LDG/STS: instr i covers warp-local rows 4i..4i+3;
    // lane l -> row 4i + (l>>3), float cols (l&7)*4 .. +3
    const int rl = l >> 3;
    const int cl = (l & 7) * 4;
    const int kbsts = cl * 2;                       // byte col of this lane's 8B
    const uint32_t gsts = (uint32_t)(kbsts >> 4);   // granule
    const uint32_t hsts = (uint32_t)(kbsts & 15);
    const float* xr = x + (size_t)bt * 128 * NC + (size_t)(32 * w + rl) * NC
                        + (size_t)q * NS + cl;
    char* aHiW = (char*)&sAhi[w][0];
    char* aLoW = (char*)&sAlo[w][0];

    float4 g[8];
    #pragma unroll
    for (int i = 0; i < 8; i++)
        g[i] = *(const float4*)(xr + (size_t)(4 * i) * NC);  // chunk 0

    for (int c = 0; c < 4; c++) {
        // ---- convert + swizzled STS into warp-private region ----
        #pragma unroll
        for (int i = 0; i < 8; i++) {
            float4 v = g[i];
            uint32_t h01 = bf2pack(v.x, v.y);
            uint32_t h23 = bf2pack(v.z, v.w);
            float e0 = v.x - __uint_as_float(h01 << 16);
            float e1 = v.y - __uint_as_float(h01 & 0xFFFF0000u);
            float e2 = v.z - __uint_as_float(h23 << 16);
            float e3 = v.w - __uint_as_float(h23 & 0xFFFF0000u);
            uint32_t l01 = bf2pack(e0, e1);
            uint32_t l23 = bf2pack(e2, e3);
            int r = 4 * i + rl;
            uint32_t sw = (uint32_t)(r << 6)
                        + (((gsts ^ (uint32_t)((r >> 1) & 3)) << 4)) + hsts;
            *(uint2*)(aHiW + sw) = make_uint2(h01, h23);
            *(uint2*)(aLoW + sw) = make_uint2(l01, l23);
        }
        // ---- prefetch next chunk under this chunk's MMAs ----
        if (c < 3) {
            #pragma unroll
            for (int i = 0; i < 8; i++)
                g[i] = *(const float4*)(xr + (size_t)(4 * i) * NC + (c + 1) * 32);
        }
        __syncwarp();

        // ---- 2 k16 steps of MMA ----
        #pragma unroll
        for (int ks = 0; ks < 2; ks++) {
            const uint32_t gA = (uint32_t)(2 * ks + lkg);          // A k-granule (chunk-local)
            const uint32_t gB = (uint32_t)(4 * c + 2 * ks + lkg);  // B k-granule (global K)
            const uint32_t aoff = ((gA ^ vA) << 4);
            const uint32_t boff = ((gB ^ vB) << 4);
            uint32_t ah0[4], ah1[4], al0[4], al1[4];
            uint32_t bh0[4], bh1[4], bl0[4], bl1[4];
            ldsm4(ah0, aHi + aoff);
            ldsm4(ah1, aHi + aoff + 16 * 64);
            ldsm4(al0, aLo + aoff);
            ldsm4(al1, aLo + aoff + 16 * 64);
            ldsm4(bh0, bHi + boff);
            ldsm4(bh1, bHi + boff + 16 * 256);
            ldsm4(bl0, bLo + boff);
            ldsm4(bl1, bLo + boff + 16 * 256);
            uint32_t bh_0[4] = {bh0[0], bh0[1], bh1[0], bh1[1]};
            uint32_t bh_1[4] = {bh0[2], bh0[3], bh1[2], bh1[3]};
            uint32_t bl_0[4] = {bl0[0], bl0[1], bl1[0], bl1[1]};
            uint32_t bl_1[4] = {bl0[2], bl0[3], bl1[2], bl1[3]};
            #pragma unroll
            for (int nj = 0; nj < 4; nj++) {
                mma_bf16(acc[0][nj], ah0, bh_0[nj], bh_1[nj]);
                mma_bf16(acc[1][nj], ah1, bh_0[nj], bh_1[nj]);
                mma_bf16(acc[0][nj], ah0, bl_0[nj], bl_1[nj]);
                mma_bf16(acc[1][nj], ah1, bl_0[nj], bl_1[nj]);
                mma_bf16(acc[0][nj], al0, bh_0[nj], bh_1[nj]);
                mma_bf16(acc[1][nj], al1, bh_0[nj], bh_1[nj]);
            }
        }
        __syncwarp();  // LDSM of chunk c done before STS of chunk c+1
    }

    // ---- epilogue: +b1, ELU, dot W2, quad-reduce, store ----
    const int gg = l >> 2;
    const int qd = l & 3;
    #pragma unroll
    for (int mi = 0; mi < 2; mi++) {
        float pa = 0.0f, pb = 0.0f;
        #pragma unroll
        for (int nj = 0; nj < 4; nj++) {
            int h0 = nj * 8 + qd * 2, h1 = h0 + 1;
            float b10 = sB1[h0], b11 = sB1[h1];
            float w20 = sW2[h0], w21 = sW2[h1];
            float v0 = acc[mi][nj][0] + b10;
            float v1 = acc[mi][nj][1] + b11;
            float v2 = acc[mi][nj][2] + b10;
            float v3 = acc[mi][nj][3] + b11;
            pa += ((v0 > 0.0f) ? v0 : (__expf(v0) - 1.0f)) * w20;
            pa += ((v1 > 0.0f) ? v1 : (__expf(v1) - 1.0f)) * w21;
            pb += ((v2 > 0.0f) ? v2 : (__expf(v2) - 1.0f)) * w20;
            pb += ((v3 > 0.0f) ? v3 : (__expf(v3) - 1.0f)) * w21;
        }
        pa += __shfl_xor_sync(0xFFFFFFFFu, pa, 1);
        pa += __shfl_xor_sync(0xFFFFFFFFu, pa, 2);
        pb += __shfl_xor_sync(0xFFFFFFFFu, pb, 1);
        pb += __shfl_xor_sync(0xFFFFFFFFu, pb, 2);
        if (qd == 0) {
            int r0 = w * 32 + mi * 16 + gg;
            out[((size_t)bt * 128 + r0) * NQ + q] = pa + sB2v;
            out[((size_t)bt * 128 + r0 + 8) * NQ + q] = pb + sB2v;
        }
    }
}

extern "C" void kernel_launch(void* const* d_in, const int* in_sizes, int n_in,
                              void* d_out, int out_size) {
    const float* x  = (const float*)d_in[0];
    const float* W1 = (const float*)d_in[1];
    const float* b1 = (const float*)d_in[2];
    const float* W2 = (const float*)d_in[3];
    const float* b2 = (const float*)d_in[4];
    float* out = (float*)d_out;

    dim3 grid(NQ, NB / 128);  // 128 q x 16 batch tiles
    divenc_mma<<<grid, TPB>>>(x, W1, b1, W2, b2, out);
}

// round 9
// speedup vs baseline: 2.7405x; 1.1120x over previous
#include <cuda_runtime.h>
#include <cuda_bf16.h>
#include <cstdint>

// B=2048, Q=128, S=128(K), H=32(N)
#define NB 2048
#define NQ 128
#define NS 128
#define NH 32
#define NC (NQ * NS)
#define TPB 128

__device__ __forceinline__ uint32_t smem_u32(const void* p) {
    uint32_t a;
    asm("{ .reg .u64 t; cvta.to.shared.u64 t, %1; cvt.u32.u64 %0, t; }" : "=r"(a) : "l"(p));
    return a;
}
__device__ __forceinline__ void ldsm4(uint32_t* r, uint32_t addr) {
    asm volatile("ldmatrix.sync.aligned.m8n8.x4.shared.b16 {%0,%1,%2,%3}, [%4];"
                 : "=r"(r[0]), "=r"(r[1]), "=r"(r[2]), "=r"(r[3]) : "r"(addr));
}
__device__ __forceinline__ void mma_bf16(float* d, const uint32_t* a, uint32_t b0, uint32_t b1) {
    asm volatile(
        "mma.sync.aligned.m16n8k16.row.col.f32.bf16.bf16.f32 "
        "{%0,%1,%2,%3}, {%4,%5,%6,%7}, {%8,%9}, {%0,%1,%2,%3};"
        : "+f"(d[0]), "+f"(d[1]), "+f"(d[2]), "+f"(d[3])
        : "r"(a[0]), "r"(a[1]), "r"(a[2]), "r"(a[3]), "r"(b0), "r"(b1));
}
// pack {hi half = y, lo half = x} as bf16x2
__device__ __forceinline__ uint32_t bf2pack(float x, float y) {
    uint32_t r;
    asm("cvt.rn.bf16x2.f32 %0, %1, %2;" : "=r"(r) : "f"(y), "f"(x));
    return r;
}

// A smem: per-warp 32 rows x 64B (32 k bf16), swizzle granule g^((r>>1)&3).
// B smem: 32 rows x 256B (full K=128 bf16), swizzle granule g^(r&7).
// Both conflict-free for STS and LDSM (verified R7).

__global__ __launch_bounds__(TPB, 4) void divenc_mma(
    const float* __restrict__ x, const float* __restrict__ W1,
    const float* __restrict__ b1, const float* __restrict__ W2,
    const float* __restrict__ b2, float* __restrict__ out)
{
    __shared__ __align__(16) __nv_bfloat16 sAhi[4][32 * 32];  // 8KB
    __shared__ __align__(16) __nv_bfloat16 sAlo[4][32 * 32];  // 8KB
    __shared__ __align__(16) __nv_bfloat16 sBhi[NH * NS];     // 8KB
    __shared__ __align__(16) __nv_bfloat16 sBlo[NH * NS];     // 8KB
    __shared__ float sB1[NH], sW2[NH];
    __shared__ float sB2v;

    const int q = blockIdx.x;
    const int bt = blockIdx.y;
    const int t = threadIdx.x;
    const int w = t >> 5;
    const int l = t & 31;

    // LDG/STS mapping for x: instr i covers warp-local rows 4i..4i+3;
    // lane l -> row 4i + (l>>3), float cols (l&7)*4 .. +3
    const int rl = l >> 3;
    const int cl = (l & 7) * 4;
    const float* xr = x + (size_t)bt * 128 * NC + (size_t)(32 * w + rl) * NC
                        + (size_t)q * NS + cl;

    // ---- prefetch x chunk 0 FIRST: DRAM latency hides under B staging ----
    float4 g[8];
    #pragma unroll
    for (int i = 0; i < 8; i++)
        g[i] = *(const float4*)(xr + (size_t)(4 * i) * NC);

    // ---- stage B = W1[q]^T full-K (hi/lo bf16, swizzled), conflict-free ----
    // Thread handles h = lane, 8 consecutive k (one 16B swizzle granule):
    // STS.128 per 8-lane phase hits 8 distinct bank-groups -> 0 conflicts.
    const float* gW = W1 + (size_t)q * NS * NH;
    char* bHiC = (char*)sBhi;
    char* bLoC = (char*)sBlo;
    #pragma unroll
    for (int i = 0; i < 4; i++) {
        int ko = 4 * i + w;                       // k-octet 0..15
        const float* wp = gW + (size_t)(ko * 8) * NH + l;  // h = l
        float wv[8];
        #pragma unroll
        for (int j = 0; j < 8; j++) wv[j] = wp[j * NH];
        uint32_t hh[4], ll[4];
        #pragma unroll
        for (int j = 0; j < 4; j++) {
            uint32_t hp = bf2pack(wv[2 * j], wv[2 * j + 1]);
            float e0 = wv[2 * j]     - __uint_as_float(hp << 16);
            float e1 = wv[2 * j + 1] - __uint_as_float(hp & 0xFFFF0000u);
            hh[j] = hp;
            ll[j] = bf2pack(e0, e1);
        }
        uint32_t sw = (uint32_t)(l * 256) + (uint32_t)(((ko ^ (l & 7)) << 4));
        *(uint4*)(bHiC + sw) = make_uint4(hh[0], hh[1], hh[2], hh[3]);
        *(uint4*)(bLoC + sw) = make_uint4(ll[0], ll[1], ll[2], ll[3]);
    }
    if (t < NH) { sB1[t] = b1[q * NH + t]; sW2[t] = W2[q * NH + t]; }
    if (t == 0) sB2v = b2[q];
    __syncthreads();   // the ONLY block-wide barrier

    float acc[2][4][4];
    #pragma unroll
    for (int mi = 0; mi < 2; mi++)
        #pragma unroll
        for (int nj = 0; nj < 4; nj++)
            #pragma unroll
            for (int c = 0; c < 4; c++) acc[mi][nj][c] = 0.0f;

    // ldmatrix lane params (non-trans, verified mapping)
    const int lr = l & 15;
    const int lkg = l >> 4;       // k-granule half: 0 -> k0-7, 1 -> k8-15
    const uint32_t vA = (uint32_t)((lr >> 1) & 3);
    const uint32_t vB = (uint32_t)(lr & 7);
    const uint32_t aHi = smem_u32(&sAhi[w][0]) + (uint32_t)lr * 64;
    const uint32_t aLo = smem_u32(&sAlo[w][0]) + (uint32_t)lr * 64;
    const uint32_t bHi = smem_u32(sBhi) + (uint32_t)lr * 256;
    const uint32_t bLo = smem_u32(sBlo) + (uint32_t)lr * 256;

    const int kbsts = cl * 2;                       // byte col of this lane's 8B
    const uint32_t gsts = (uint32_t)(kbsts >> 4);   // granule
    const uint32_t hsts = (uint32_t)(kbsts & 15);
    char* aHiW = (char*)&sAhi[w][0];
    char* aLoW = (char*)&sAlo[w][0];

    for (int c = 0; c < 4; c++) {
        // ---- convert + swizzled STS into warp-private region ----
        #pragma unroll
        for (int i = 0; i < 8; i++) {
            float4 v = g[i];
            uint32_t h01 = bf2pack(v.x, v.y);
            uint32_t h23 = bf2pack(v.z, v.w);
            float e0 = v.x - __uint_as_float(h01 << 16);
            float e1 = v.y - __uint_as_float(h01 & 0xFFFF0000u);
            float e2 = v.z - __uint_as_float(h23 << 16);
            float e3 = v.w - __uint_as_float(h23 & 0xFFFF0000u);
            uint32_t l01 = bf2pack(e0, e1);
            uint32_t l23 = bf2pack(e2, e3);
            int r = 4 * i + rl;
            uint32_t sw = (uint32_t)(r << 6)
                        + (((gsts ^ (uint32_t)((r >> 1) & 3)) << 4)) + hsts;
            *(uint2*)(aHiW + sw) = make_uint2(h01, h23);
            *(uint2*)(aLoW + sw) = make_uint2(l01, l23);
        }
        // ---- prefetch next chunk under this chunk's MMAs ----
        if (c < 3) {
            #pragma unroll
            for (int i = 0; i < 8; i++)
                g[i] = *(const float4*)(xr + (size_t)(4 * i) * NC + (c + 1) * 32);
        }
        __syncwarp();

        // ---- 2 k16 steps of MMA ----
        #pragma unroll
        for (int ks = 0; ks < 2; ks++) {
            const uint32_t gA = (uint32_t)(2 * ks + lkg);          // A k-granule (chunk-local)
            const uint32_t gB = (uint32_t)(4 * c + 2 * ks + lkg);  // B k-granule (global K)
            const uint32_t aoff = ((gA ^ vA) << 4);
            const uint32_t boff = ((gB ^ vB) << 4);
            uint32_t ah0[4], ah1[4], al0[4], al1[4];
            uint32_t bh0[4], bh1[4], bl0[4], bl1[4];
            ldsm4(ah0, aHi + aoff);
            ldsm4(ah1, aHi + aoff + 16 * 64);
            ldsm4(al0, aLo + aoff);
            ldsm4(al1, aLo + aoff + 16 * 64);
            ldsm4(bh0, bHi + boff);
            ldsm4(bh1, bHi + boff + 16 * 256);
            ldsm4(bl0, bLo + boff);
            ldsm4(bl1, bLo + boff + 16 * 256);
            uint32_t bh_0[4] = {bh0[0], bh0[1], bh1[0], bh1[1]};
            uint32_t bh_1[4] = {bh0[2], bh0[3], bh1[2], bh1[3]};
            uint32_t bl_0[4] = {bl0[0], bl0[1], bl1[0], bl1[1]};
            uint32_t bl_1[4] = {bl0[2], bl0[3], bl1[2], bl1[3]};
            #pragma unroll
            for (int nj = 0; nj < 4; nj++) {
                mma_bf16(acc[0][nj], ah0, bh_0[nj], bh_1[nj]);
                mma_bf16(acc[1][nj], ah1, bh_0[nj], bh_1[nj]);
                mma_bf16(acc[0][nj], ah0, bl_0[nj], bl_1[nj]);
                mma_bf16(acc[1][nj], ah1, bl_0[nj], bl_1[nj]);
                mma_bf16(acc[0][nj], al0, bh_0[nj], bh_1[nj]);
                mma_bf16(acc[1][nj], al1, bh_0[nj], bh_1[nj]);
            }
        }
        __syncwarp();  // LDSM of chunk c done before STS of chunk c+1
    }

    // ---- epilogue: +b1, ELU, dot W2, quad-reduce, store ----
    const int gg = l >> 2;
    const int qd = l & 3;
    #pragma unroll
    for (int mi = 0; mi < 2; mi++) {
        float pa = 0.0f, pb = 0.0f;
        #pragma unroll
        for (int nj = 0; nj < 4; nj++) {
            int h0 = nj * 8 + qd * 2, h1 = h0 + 1;
            float b10 = sB1[h0], b11 = sB1[h1];
            float w20 = sW2[h0], w21 = sW2[h1];
            float v0 = acc[mi][nj][0] + b10;
            float v1 = acc[mi][nj][1] + b11;
            float v2 = acc[mi][nj][2] + b10;
            float v3 = acc[mi][nj][3] + b11;
            pa += ((v0 > 0.0f) ? v0 : (__expf(v0) - 1.0f)) * w20;
            pa += ((v1 > 0.0f) ? v1 : (__expf(v1) - 1.0f)) * w21;
            pb += ((v2 > 0.0f) ? v2 : (__expf(v2) - 1.0f)) * w20;
            pb += ((v3 > 0.0f) ? v3 : (__expf(v3) - 1.0f)) * w21;
        }
        pa += __shfl_xor_sync(0xFFFFFFFFu, pa, 1);
        pa += __shfl_xor_sync(0xFFFFFFFFu, pa, 2);
        pb += __shfl_xor_sync(0xFFFFFFFFu, pb, 1);
        pb += __shfl_xor_sync(0xFFFFFFFFu, pb, 2);
        if (qd == 0) {
            int r0 = w * 32 + mi * 16 + gg;
            out[((size_t)bt * 128 + r0) * NQ + q] = pa + sB2v;
            out[((size_t)bt * 128 + r0 + 8) * NQ + q] = pb + sB2v;
        }
    }
}

extern "C" void kernel_launch(void* const* d_in, const int* in_sizes, int n_in,
                              void* d_out, int out_size) {
    const float* x  = (const float*)d_in[0];
    const float* W1 = (const float*)d_in[1];
    const float* b1 = (const float*)d_in[2];
    const float* W2 = (const float*)d_in[3];
    const float* b2 = (const float*)d_in[4];
    float* out = (float*)d_out;

    dim3 grid(NQ, NB / 128);  // 128 q x 16 batch tiles
    divenc_mma<<<grid, TPB>>>(x, W1, b1, W2, b2, out);
}